// round 13
// baseline (speedup 1.0000x reference)
#include <cuda_runtime.h>
#include <cuda_bf16.h>
#include <mma.h>
#include <cstdint>

using namespace nvcuda;

#define N_NODES 100000
#define N_PAD   100096               // 782 * 128
#define N_EDGES 1600000
#define D_IN    256
#define D_EDGE  16
#define D_OUT   128

#define SCAN_BLK  1024
#define SCAN_NB   ((N_NODES + SCAN_BLK - 1) / SCAN_BLK)   // 98

// Scratch (allocation-free rule: __device__ globals; zero-initialized)
__device__ __nv_bfloat16      g_Hb[(size_t)N_NODES * D_OUT]; // X @ W_neigh (bf16)
__device__ __nv_bfloat16      g_Xhi[(size_t)N_PAD * D_IN];   // X split hi (pad rows stay 0)
__device__ __nv_bfloat16      g_Xlo[(size_t)N_PAD * D_IN];   // X split lo
__device__ __nv_bfloat16      g_Whi[D_IN * 256];             // [k][c]: c<128 Wn, else Ws (hi)
__device__ __nv_bfloat16      g_Wlo[D_IN * 256];             // (lo)
__device__ int                g_deg[N_NODES + 1];            // in-degree; [N_NODES] = scan base
__device__ int                g_off[N_NODES];                // CSR offsets
__device__ int                g_cursor[N_NODES];             // scatter cursors
__device__ unsigned long long g_list[N_EDGES];               // packed (e*16)<<32 | (s*128)

__device__ __forceinline__ uint32_t pack_bf16(__nv_bfloat16 a, __nv_bfloat16 b) {
    __nv_bfloat162 t(a, b);
    return *reinterpret_cast<uint32_t*>(&t);
}
__device__ __forceinline__ void split_bf16(float x, __nv_bfloat16& hi, __nv_bfloat16& lo) {
    hi = __float2bfloat16(x);
    lo = __float2bfloat16(x - __bfloat162float(hi));
}
__device__ __forceinline__ void cp_async16(uint32_t smem_addr, const void* gptr) {
    asm volatile("cp.async.cg.shared.global [%0], [%1], 16;"
                 :: "r"(smem_addr), "l"(gptr));
}
#define CP_COMMIT() asm volatile("cp.async.commit_group;")
#define CP_WAIT(n)  asm volatile("cp.async.wait_group %0;" :: "n"(n))

// ---------------------------------------------------------------------------
// Fused prep: blocks [0,64) = W pre-split; [64, 64+XS_BLOCKS) = X pre-split;
// rest = dst histogram. All independent.
// ---------------------------------------------------------------------------
#define XS_BLOCKS  ((N_NODES * (D_IN / 16)) / 256)    // 6250
#define HIST_BLOCKS ((N_EDGES / 4 + 255) / 256)       // 1563
#define PREP_BLOCKS (64 + XS_BLOCKS + HIST_BLOCKS)

__global__ __launch_bounds__(256)
void prep_kernel(const float* __restrict__ X,
                 const float* __restrict__ Wn, const float* __restrict__ Ws,
                 const int* __restrict__ dst) {
    if (blockIdx.x < 64) {
        const int i = blockIdx.x * 256 + threadIdx.x;
        const int k = i >> 6;            // 0..255
        const int c = (i & 63) * 4;      // 0..252
        const float4 v = (c < 128)
                       ? *(const float4*)(Wn + (size_t)k * D_OUT + c)
                       : *(const float4*)(Ws + (size_t)k * D_OUT + (c - 128));
        __nv_bfloat16 h0,h1,h2,h3,l0,l1,l2,l3;
        split_bf16(v.x, h0, l0); split_bf16(v.y, h1, l1);
        split_bf16(v.z, h2, l2); split_bf16(v.w, h3, l3);
        *(uint2*)(g_Whi + k * 256 + c) = make_uint2(pack_bf16(h0,h1), pack_bf16(h2,h3));
        *(uint2*)(g_Wlo + k * 256 + c) = make_uint2(pack_bf16(l0,l1), pack_bf16(l2,l3));
    } else if (blockIdx.x < 64 + XS_BLOCKS) {
        // X split: each thread converts 16 floats of one row
        const int i = (blockIdx.x - 64) * 256 + threadIdx.x;
        const int row   = i >> 4;              // 0..99999
        const int col16 = (i & 15) * 16;       // 0..240
        const float* xp = X + (size_t)row * D_IN + col16;
        uint4 vh[2], vl[2];
        #pragma unroll
        for (int q = 0; q < 2; q++) {
            const float4 a = *(const float4*)(xp + q * 8 + 0);
            const float4 b = *(const float4*)(xp + q * 8 + 4);
            __nv_bfloat16 h[8], l[8];
            split_bf16(a.x, h[0], l[0]); split_bf16(a.y, h[1], l[1]);
            split_bf16(a.z, h[2], l[2]); split_bf16(a.w, h[3], l[3]);
            split_bf16(b.x, h[4], l[4]); split_bf16(b.y, h[5], l[5]);
            split_bf16(b.z, h[6], l[6]); split_bf16(b.w, h[7], l[7]);
            vh[q] = make_uint4(pack_bf16(h[0],h[1]), pack_bf16(h[2],h[3]),
                               pack_bf16(h[4],h[5]), pack_bf16(h[6],h[7]));
            vl[q] = make_uint4(pack_bf16(l[0],l[1]), pack_bf16(l[2],l[3]),
                               pack_bf16(l[4],l[5]), pack_bf16(l[6],l[7]));
        }
        __nv_bfloat16* dh = g_Xhi + (size_t)row * D_IN + col16;
        __nv_bfloat16* dl = g_Xlo + (size_t)row * D_IN + col16;
        *(uint4*)(dh + 0) = vh[0];
        *(uint4*)(dh + 8) = vh[1];
        *(uint4*)(dl + 0) = vl[0];
        *(uint4*)(dl + 8) = vl[1];
    } else {
        const int i = (blockIdx.x - 64 - XS_BLOCKS) * 256 + threadIdx.x;
        if (i * 4 + 3 < N_EDGES) {
            const int4 d4 = *(const int4*)(dst + i * 4);
            atomicAdd(&g_deg[d4.x], 1);
            atomicAdd(&g_deg[d4.y], 1);
            atomicAdd(&g_deg[d4.z], 1);
            atomicAdd(&g_deg[d4.w], 1);
        } else {
            for (int e = i * 4; e < N_EDGES; ++e)
                atomicAdd(&g_deg[dst[e]], 1);
        }
    }
}

// ---------------------------------------------------------------------------
// CSR: one-shot scan. Block-local Hillis-Steele + atomic base grab.
// ---------------------------------------------------------------------------
__global__ __launch_bounds__(SCAN_BLK)
void scan_kernel() {
    __shared__ int s[SCAN_BLK];
    __shared__ int base;
    const int t = threadIdx.x;
    const int i = blockIdx.x * SCAN_BLK + t;
    const int d = (i < N_NODES) ? g_deg[i] : 0;
    s[t] = d;
    __syncthreads();
    #pragma unroll
    for (int off = 1; off < SCAN_BLK; off <<= 1) {
        int v = (t >= off) ? s[t - off] : 0;
        __syncthreads();
        s[t] += v;
        __syncthreads();
    }
    if (t == SCAN_BLK - 1) base = atomicAdd(&g_deg[N_NODES], s[t]);
    __syncthreads();
    if (i < N_NODES) {
        const int o = base + s[t] - d;
        g_off[i] = o;
        g_cursor[i] = o;
    }
}

// ---------------------------------------------------------------------------
// Fused launch: blocks [0, GEMM_BLOCKS) = wmma node GEMM — fully cp.async
// (A from g_Xhi/g_Xlo, B from g_Whi/g_Wlo), 3-deep pipeline, one sync/chunk.
// Rest = CSR scatter (int4).
// ---------------------------------------------------------------------------
#define TILE_M 128
#define KC     32
#define NCHUNK (D_IN / KC)   // 8
#define LDA    40            // As row stride (bf16), 80B
#define LDB    264           // Bs row stride (bf16), 528B
#define A_BYTES   10240      // 128*40*2
#define OFF_A_LO  10240
#define OFF_B_HI  20480
#define BS_BYTES  16896      // 32*264*2
#define OFF_B_LO  37376
#define BUF_STRIDE 54272
#define NBUF 3
#define GEMM_SMEM (NBUF * BUF_STRIDE)   // 162816

#define GEMM_BLOCKS (N_PAD / TILE_M)                         // 782
#define SCAT_BLOCKS ((N_EDGES / 4 + 511) / 512)              // 782

__global__ __launch_bounds__(512)
void gemm_scatter_kernel(float* __restrict__ out,
                         const int* __restrict__ src,
                         const int* __restrict__ dst) {
    // ---------------- scatter partition (4 edges per thread, int4) ----------
    if (blockIdx.x >= GEMM_BLOCKS) {
        const int q = (blockIdx.x - GEMM_BLOCKS) * 512 + threadIdx.x;
        const int e0 = q * 4;
        if (e0 + 3 < N_EDGES) {
            const int4 s4 = ((const int4*)src)[q];
            const int4 d4 = ((const int4*)dst)[q];
            int p;
            p = atomicAdd(&g_cursor[d4.x], 1);
            g_list[p] = ((unsigned long long)(unsigned)((e0+0) * D_EDGE) << 32) | (unsigned)(s4.x * D_OUT);
            p = atomicAdd(&g_cursor[d4.y], 1);
            g_list[p] = ((unsigned long long)(unsigned)((e0+1) * D_EDGE) << 32) | (unsigned)(s4.y * D_OUT);
            p = atomicAdd(&g_cursor[d4.z], 1);
            g_list[p] = ((unsigned long long)(unsigned)((e0+2) * D_EDGE) << 32) | (unsigned)(s4.z * D_OUT);
            p = atomicAdd(&g_cursor[d4.w], 1);
            g_list[p] = ((unsigned long long)(unsigned)((e0+3) * D_EDGE) << 32) | (unsigned)(s4.w * D_OUT);
        } else {
            for (int e = e0; e < N_EDGES; ++e) {
                const int p2 = atomicAdd(&g_cursor[dst[e]], 1);
                g_list[p2] = ((unsigned long long)(unsigned)(e * D_EDGE) << 32)
                           | (unsigned)(src[e] * D_OUT);
            }
        }
        return;
    }

    // ---------------- GEMM partition ----------------
    extern __shared__ char smem[];
    uint32_t sbase;
    asm("{ .reg .u64 t; cvta.to.shared.u64 t, %1; cvt.u32.u64 %0, t; }"
        : "=r"(sbase) : "l"(smem));

    const int tid  = threadIdx.x;
    const int wid  = tid >> 5;
    const int lane = tid & 31;
    const int warp_m = wid & 3;      // 4 warps in M (32 rows each)
    const int warp_n = wid >> 2;     // 4 warps in N (64 cols each)
    const int rowBase = blockIdx.x * TILE_M;

    // A copier: 128 rows x 32 cols bf16, 16B (8 bf16) per thread per buffer
    const int arow = tid >> 2;            // 0..127
    const int acol = (tid & 3) * 8;       // 0,8,16,24
    const int aSOff = arow * (LDA * 2) + acol * 2;              // smem byte offset
    const size_t aGOff = (size_t)(rowBase + arow) * D_IN + acol; // global elem offset
    // B copier: 32 rows x 256 cols, 2x16B per thread per buffer
    const int brow = tid >> 4;            // 0..31
    const int bcol = (tid & 15) * 16;     // 0..240
    const int bSOff = (brow * LDB + bcol) * 2;

    wmma::fragment<wmma::accumulator, 16, 16, 16, float> acc[2][4];
    #pragma unroll
    for (int m = 0; m < 2; m++)
        #pragma unroll
        for (int n = 0; n < 4; n++)
            wmma::fill_fragment(acc[m][n], 0.0f);

    // issue chunk c into buffer b
    auto issue = [&](int c, int b) {
        const uint32_t bb = sbase + b * BUF_STRIDE;
        const int k0 = c * KC;
        cp_async16(bb + aSOff,            g_Xhi + aGOff + k0);
        cp_async16(bb + OFF_A_LO + aSOff, g_Xlo + aGOff + k0);
        const int g = (k0 + brow) * 256 + bcol;
        cp_async16(bb + OFF_B_HI + bSOff,      g_Whi + g);
        cp_async16(bb + OFF_B_HI + bSOff + 16, g_Whi + g + 8);
        cp_async16(bb + OFF_B_LO + bSOff,      g_Wlo + g);
        cp_async16(bb + OFF_B_LO + bSOff + 16, g_Wlo + g + 8);
        CP_COMMIT();
    };

    issue(0, 0);
    issue(1, 1);

    for (int c = 0; c < NCHUNK; ++c) {
        if (c + 1 < NCHUNK) { CP_WAIT(1); } else { CP_WAIT(0); }
        __syncthreads();

        const char* buf = smem + (c % NBUF) * BUF_STRIDE;
        const __nv_bfloat16* As_hi = (const __nv_bfloat16*)(buf);
        const __nv_bfloat16* As_lo = (const __nv_bfloat16*)(buf + OFF_A_LO);
        const __nv_bfloat16* Bs_hi = (const __nv_bfloat16*)(buf + OFF_B_HI);
        const __nv_bfloat16* Bs_lo = (const __nv_bfloat16*)(buf + OFF_B_LO);

        #pragma unroll
        for (int ks = 0; ks < KC / 16; ks++) {
            wmma::fragment<wmma::matrix_a, 16, 16, 16, __nv_bfloat16, wmma::row_major> a_hi[2], a_lo[2];
            #pragma unroll
            for (int m = 0; m < 2; m++) {
                wmma::load_matrix_sync(a_hi[m], As_hi + (warp_m * 32 + m * 16) * LDA + ks * 16, LDA);
                wmma::load_matrix_sync(a_lo[m], As_lo + (warp_m * 32 + m * 16) * LDA + ks * 16, LDA);
            }
            #pragma unroll
            for (int n = 0; n < 4; n++) {
                wmma::fragment<wmma::matrix_b, 16, 16, 16, __nv_bfloat16, wmma::row_major> b_hi, b_lo;
                wmma::load_matrix_sync(b_hi, Bs_hi + (ks * 16) * LDB + warp_n * 64 + n * 16, LDB);
                wmma::load_matrix_sync(b_lo, Bs_lo + (ks * 16) * LDB + warp_n * 64 + n * 16, LDB);
                #pragma unroll
                for (int m = 0; m < 2; m++) {
                    wmma::mma_sync(acc[m][n], a_hi[m], b_hi, acc[m][n]);
                    wmma::mma_sync(acc[m][n], a_hi[m], b_lo, acc[m][n]);
                    wmma::mma_sync(acc[m][n], a_lo[m], b_hi, acc[m][n]);
                }
            }
        }

        if (c + 2 < NCHUNK) issue(c + 2, (c + 2) % NBUF);
    }
    __syncthreads();   // before reusing smem for the epilogue stage

    // ---- Epilogue: cols 0-127 -> g_Hb (bf16, staged), 128-255 -> out (fp32) ----
    const bool fullTile = (rowBase + TILE_M <= N_NODES);
    float* stage = (float*)smem + wid * 256;   // per-warp 1KB
    #pragma unroll
    for (int m = 0; m < 2; m++)
        #pragma unroll
        for (int n = 0; n < 4; n++) {
            const int row = rowBase + warp_m * 32 + m * 16;
            const int col = warp_n * 64 + n * 16;
            if (col < 128) {
                wmma::store_matrix_sync(stage, acc[m][n], 16, wmma::mem_row_major);
                __syncwarp();
                const int r  = lane >> 1;
                const int cc = (lane & 1) * 8;
                const int grow = row + r;
                if (grow < N_NODES) {
                    float4 a = *(float4*)(stage + r * 16 + cc + 0);
                    float4 b2 = *(float4*)(stage + r * 16 + cc + 4);
                    uint4 v = make_uint4(
                        pack_bf16(__float2bfloat16(a.x),  __float2bfloat16(a.y)),
                        pack_bf16(__float2bfloat16(a.z),  __float2bfloat16(a.w)),
                        pack_bf16(__float2bfloat16(b2.x), __float2bfloat16(b2.y)),
                        pack_bf16(__float2bfloat16(b2.z), __float2bfloat16(b2.w)));
                    *(uint4*)(g_Hb + (size_t)grow * D_OUT + col + cc) = v;
                }
                __syncwarp();
            } else if (fullTile) {
                wmma::store_matrix_sync(out + (size_t)row * D_OUT + (col - 128),
                                        acc[m][n], D_OUT, wmma::mem_row_major);
            } else {
                wmma::store_matrix_sync(stage, acc[m][n], 16, wmma::mem_row_major);
                __syncwarp();
                const int r  = lane >> 1;
                const int cc = (lane & 1) * 8;
                const int grow = row + r;
                if (grow < N_NODES) {
                    float* p = out + (size_t)grow * D_OUT + (col - 128) + cc;
                    *(float4*)(p + 0) = *(float4*)(stage + r * 16 + cc + 0);
                    *(float4*)(p + 4) = *(float4*)(stage + r * 16 + cc + 4);
                }
                __syncwarp();
            }
        }
}

// ---------------------------------------------------------------------------
// Aggregate: one warp per dst node (grid-stride). Atomic-free, 8-edge unroll.
// ---------------------------------------------------------------------------
__device__ __forceinline__ void acc_bf16x4(float4& h, uint2 u) {
    const float2 a = __bfloat1622float2(*reinterpret_cast<__nv_bfloat162*>(&u.x));
    const float2 b = __bfloat1622float2(*reinterpret_cast<__nv_bfloat162*>(&u.y));
    h.x += a.x; h.y += a.y; h.z += b.x; h.w += b.y;
}

__global__ __launch_bounds__(256, 4)
void aggregate_kernel(const float* __restrict__ Xe,
                      const float* __restrict__ We,    // [16][128]
                      const float* __restrict__ bias,
                      float* __restrict__ out) {
    __shared__ float4 sW[D_EDGE][32];   // [k][lane], 8KB

    const int tid  = threadIdx.x;
    const int lane = tid & 31;
    const int col  = lane * 4;

    for (int i = tid; i < D_EDGE * 32; i += 256) {
        const int k = i >> 5, l = i & 31;
        sW[k][l] = *(const float4*)(We + k * D_OUT + l * 4);
    }
    __syncthreads();

    const float4 b = *(const float4*)(bias + col);

    const int warpId = (blockIdx.x * blockDim.x + tid) >> 5;
    const int nWarps = (gridDim.x * blockDim.x) >> 5;

    for (int d = warpId; d < N_NODES; d += nWarps) {
        const int start = g_off[d];
        const int c     = g_deg[d];

        float4 h = make_float4(0.f, 0.f, 0.f, 0.f);
        float xacc0 = 0.f, xacc1 = 0.f, xacc2 = 0.f, xacc3 = 0.f;
        const int xl = lane & 15;

        int i = 0;
        for (; i + 8 <= c; i += 8) {
            unsigned long long pe[8];
            #pragma unroll
            for (int j = 0; j < 8; j++) pe[j] = g_list[start + i + j];

            uint2 hu[8];
            #pragma unroll
            for (int j = 0; j < 8; j++)
                hu[j] = *(const uint2*)(g_Hb + (unsigned)pe[j] + col);

            const unsigned eA = (lane < 16) ? (unsigned)(pe[0] >> 32) : (unsigned)(pe[1] >> 32);
            const unsigned eB = (lane < 16) ? (unsigned)(pe[2] >> 32) : (unsigned)(pe[3] >> 32);
            const unsigned eC = (lane < 16) ? (unsigned)(pe[4] >> 32) : (unsigned)(pe[5] >> 32);
            const unsigned eD = (lane < 16) ? (unsigned)(pe[6] >> 32) : (unsigned)(pe[7] >> 32);
            xacc0 += Xe[eA + xl];
            xacc1 += Xe[eB + xl];
            xacc2 += Xe[eC + xl];
            xacc3 += Xe[eD + xl];

            #pragma unroll
            for (int j = 0; j < 8; j++) acc_bf16x4(h, hu[j]);
        }
        for (; i + 2 <= c; i += 2) {
            const unsigned long long pe0 = g_list[start + i + 0];
            const unsigned long long pe1 = g_list[start + i + 1];
            const uint2 h0 = *(const uint2*)(g_Hb + (unsigned)pe0 + col);
            const uint2 h1 = *(const uint2*)(g_Hb + (unsigned)pe1 + col);
            const unsigned e = (lane < 16) ? (unsigned)(pe0 >> 32) : (unsigned)(pe1 >> 32);
            xacc0 += Xe[e + xl];
            acc_bf16x4(h, h0);
            acc_bf16x4(h, h1);
        }
        if (i < c) {
            const unsigned long long pe = g_list[start + i];
            const uint2 hv = *(const uint2*)(g_Hb + (unsigned)pe + col);
            acc_bf16x4(h, hv);
            if (lane < 16) xacc0 += Xe[(unsigned)(pe >> 32) + xl];
        }

        float4 o = *(const float4*)(out + (size_t)d * D_OUT + col);
        o.x += b.x; o.y += b.y; o.z += b.z; o.w += b.w;

        if (c > 0) {
            const float xs = (xacc0 + xacc1) + (xacc2 + xacc3);
            float4 p = make_float4(0.f, 0.f, 0.f, 0.f);
            #pragma unroll
            for (int k = 0; k < D_EDGE; k++) {
                const float xk = __shfl_sync(0xFFFFFFFFu, xs, k) +
                                 __shfl_sync(0xFFFFFFFFu, xs, k + 16);
                const float4 wk = sW[k][lane];
                p.x = fmaf(xk, wk.x, p.x);
                p.y = fmaf(xk, wk.y, p.y);
                p.z = fmaf(xk, wk.z, p.z);
                p.w = fmaf(xk, wk.w, p.w);
            }
            const float inv = 1.0f / (float)c;
            o.x = fmaf(h.x + p.x, inv, o.x);
            o.y = fmaf(h.y + p.y, inv, o.y);
            o.z = fmaf(h.z + p.z, inv, o.z);
            o.w = fmaf(h.w + p.w, inv, o.w);
        }
        *(float4*)(out + (size_t)d * D_OUT + col) = o;
    }
}

// ---------------------------------------------------------------------------
// Launch
// ---------------------------------------------------------------------------
extern "C" void kernel_launch(void* const* d_in, const int* in_sizes, int n_in,
                              void* d_out, int out_size) {
    const float* X    = (const float*)d_in[0];
    const float* Xe   = (const float*)d_in[1];
    const float* Wn   = (const float*)d_in[2];
    const float* Ws   = (const float*)d_in[3];
    const float* bias = (const float*)d_in[4];
    const float* We   = (const float*)d_in[5];
    const int*   src  = (const int*)d_in[6];
    const int*   dst  = (const int*)d_in[7];
    float*       out  = (float*)d_out;

    cudaFuncSetAttribute(gemm_scatter_kernel,
                         cudaFuncAttributeMaxDynamicSharedMemorySize, GEMM_SMEM);

    // 1) zero degree array + scan-base counter (memset node, no kernel)
    void* degAddr = nullptr;
    cudaGetSymbolAddress(&degAddr, g_deg);
    cudaMemsetAsync(degAddr, 0, (N_NODES + 1) * sizeof(int));

    // 2) fused W pre-split + X pre-split + dst histogram
    prep_kernel<<<PREP_BLOCKS, 256>>>(X, Wn, Ws, dst);

    // 3) one-shot scan (block scan + atomic base grab)
    scan_kernel<<<SCAN_NB, SCAN_BLK>>>();

    // 4) fused: node GEMM (g_Hb = bf16(X@Wn) ; out = X@Ws) + CSR scatter
    gemm_scatter_kernel<<<GEMM_BLOCKS + SCAT_BLOCKS, 512, GEMM_SMEM>>>(
        out, src, dst);

    // 5) gather aggregation (fuses mean, edge projection, bias, final combine)
    aggregate_kernel<<<2048, 256>>>(Xe, We, bias, out);
}

// round 14
// speedup vs baseline: 1.0272x; 1.0272x over previous
#include <cuda_runtime.h>
#include <cuda_bf16.h>
#include <mma.h>
#include <cstdint>

using namespace nvcuda;

#define N_NODES 100000
#define N_EDGES 1600000
#define D_IN    256
#define D_EDGE  16
#define D_OUT   128

#define SCAN_BLK  1024
#define SCAN_NB   ((N_NODES + SCAN_BLK - 1) / SCAN_BLK)   // 98

// Scratch (allocation-free rule: __device__ globals)
__device__ __nv_bfloat16      g_Hb[(size_t)N_NODES * D_OUT]; // X @ W_neigh (bf16)
__device__ __nv_bfloat16      g_Whi[D_IN * 256];             // [k][c]: c<128 Wn, else Ws (hi)
__device__ __nv_bfloat16      g_Wlo[D_IN * 256];             // (lo)
__device__ int                g_deg[N_NODES + 1];            // in-degree; [N_NODES] = scan base
__device__ int                g_off[N_NODES];                // CSR offsets
__device__ int                g_cursor[N_NODES];             // scatter cursors
__device__ unsigned long long g_list[N_EDGES];               // packed (e*16)<<32 | (s*128)

__device__ __forceinline__ uint32_t pack_bf16(__nv_bfloat16 a, __nv_bfloat16 b) {
    __nv_bfloat162 t(a, b);
    return *reinterpret_cast<uint32_t*>(&t);
}
__device__ __forceinline__ void split_bf16(float x, __nv_bfloat16& hi, __nv_bfloat16& lo) {
    hi = __float2bfloat16(x);
    lo = __float2bfloat16(x - __bfloat162float(hi));
}
__device__ __forceinline__ void cp_async16(uint32_t smem_addr, const void* gptr) {
    asm volatile("cp.async.cg.shared.global [%0], [%1], 16;"
                 :: "r"(smem_addr), "l"(gptr));
}
#define CP_COMMIT() asm volatile("cp.async.commit_group;")
#define CP_WAIT(n)  asm volatile("cp.async.wait_group %0;" :: "n"(n))

// packed fp32x2 add (sm_100-family PTX, plain arch)
__device__ __forceinline__ void addx2(unsigned long long& a, unsigned long long b) {
    asm("add.rn.f32x2 %0, %0, %1;" : "+l"(a) : "l"(b));
}
// bf16x2 (u32) -> packed f32x2 (u64): lo elem -> low 32, hi elem -> high 32
__device__ __forceinline__ unsigned long long bf2_to_f32x2(unsigned u) {
    return ((unsigned long long)(u & 0xFFFF0000u) << 32)
         | (unsigned long long)(u << 16);
}

// ---------------------------------------------------------------------------
// Fused prep: blocks [0,64) = W pre-split; blocks [64, ..) = dst histogram.
// ---------------------------------------------------------------------------
#define HIST_BLOCKS ((N_EDGES / 4 + 255) / 256)   // 1563

__global__ __launch_bounds__(256)
void prep_kernel(const float* __restrict__ Wn, const float* __restrict__ Ws,
                 const int* __restrict__ dst) {
    if (blockIdx.x < 64) {
        const int i = blockIdx.x * 256 + threadIdx.x;
        const int k = i >> 6;            // 0..255
        const int c = (i & 63) * 4;      // 0..252
        const float4 v = (c < 128)
                       ? *(const float4*)(Wn + (size_t)k * D_OUT + c)
                       : *(const float4*)(Ws + (size_t)k * D_OUT + (c - 128));
        __nv_bfloat16 h0,h1,h2,h3,l0,l1,l2,l3;
        split_bf16(v.x, h0, l0); split_bf16(v.y, h1, l1);
        split_bf16(v.z, h2, l2); split_bf16(v.w, h3, l3);
        *(uint2*)(g_Whi + k * 256 + c) = make_uint2(pack_bf16(h0,h1), pack_bf16(h2,h3));
        *(uint2*)(g_Wlo + k * 256 + c) = make_uint2(pack_bf16(l0,l1), pack_bf16(l2,l3));
    } else {
        const int i = (blockIdx.x - 64) * 256 + threadIdx.x;
        if (i * 4 + 3 < N_EDGES) {
            const int4 d4 = *(const int4*)(dst + i * 4);
            atomicAdd(&g_deg[d4.x], 1);
            atomicAdd(&g_deg[d4.y], 1);
            atomicAdd(&g_deg[d4.z], 1);
            atomicAdd(&g_deg[d4.w], 1);
        } else {
            for (int e = i * 4; e < N_EDGES; ++e)
                atomicAdd(&g_deg[dst[e]], 1);
        }
    }
}

// ---------------------------------------------------------------------------
// CSR: one-shot scan. Warp-shfl scan + block combine + atomic base grab.
// ---------------------------------------------------------------------------
__global__ __launch_bounds__(SCAN_BLK)
void scan_kernel() {
    __shared__ int wsum[32];
    __shared__ int base;
    const int t = threadIdx.x;
    const int w = t >> 5;
    const int lane = t & 31;
    const int i = blockIdx.x * SCAN_BLK + t;
    const int d = (i < N_NODES) ? g_deg[i] : 0;

    // warp inclusive scan
    int v = d;
    #pragma unroll
    for (int off = 1; off < 32; off <<= 1) {
        const int u = __shfl_up_sync(0xFFFFFFFFu, v, off);
        if (lane >= off) v += u;
    }
    if (lane == 31) wsum[w] = v;
    __syncthreads();
    if (w == 0) {
        int s = wsum[lane];
        #pragma unroll
        for (int off = 1; off < 32; off <<= 1) {
            const int u = __shfl_up_sync(0xFFFFFFFFu, s, off);
            if (lane >= off) s += u;
        }
        wsum[lane] = s;                      // inclusive warp sums
        if (lane == 31) base = atomicAdd(&g_deg[N_NODES], s);
    }
    __syncthreads();
    if (i < N_NODES) {
        const int pre = (w > 0) ? wsum[w - 1] : 0;
        const int o = base + pre + v - d;    // exclusive
        g_off[i] = o;
        g_cursor[i] = o;
    }
}

// ---------------------------------------------------------------------------
// Fused launch: blocks [0, GEMM_BLOCKS) = wmma node GEMM (TILE_M=128, 512thr,
// single-buffer A, cp.async double-buffered B), rest = CSR scatter (int4).
// ---------------------------------------------------------------------------
#define TILE_M 128
#define KC     32
#define NCHUNK (D_IN / KC)   // 8
#define LDA    40            // As row stride (bf16), 80B
#define LDB    264           // Bs row stride (bf16), 528B
#define OFF_AS_HI 0
#define OFF_AS_LO 10240
#define OFF_BS    20480
#define BS_BYTES  16896      // 32 * 264 * 2
#define BBUF_STRIDE (2 * BS_BYTES)   // hi+lo per buffer = 33792
#define GEMM_SMEM (OFF_BS + 2 * BBUF_STRIDE)   // 88064

#define GEMM_BLOCKS ((N_NODES + TILE_M - 1) / TILE_M)        // 782
#define SCAT_BLOCKS ((N_EDGES / 4 + 511) / 512)              // 782

__global__ __launch_bounds__(512)
void gemm_scatter_kernel(const float* __restrict__ X,
                         float* __restrict__ out,
                         const int* __restrict__ src,
                         const int* __restrict__ dst) {
    // ---------------- scatter partition (4 edges per thread, int4) ----------
    if (blockIdx.x >= GEMM_BLOCKS) {
        const int q = (blockIdx.x - GEMM_BLOCKS) * 512 + threadIdx.x;
        const int e0 = q * 4;
        if (e0 + 3 < N_EDGES) {
            const int4 s4 = ((const int4*)src)[q];
            const int4 d4 = ((const int4*)dst)[q];
            int p;
            p = atomicAdd(&g_cursor[d4.x], 1);
            g_list[p] = ((unsigned long long)(unsigned)((e0+0) * D_EDGE) << 32) | (unsigned)(s4.x * D_OUT);
            p = atomicAdd(&g_cursor[d4.y], 1);
            g_list[p] = ((unsigned long long)(unsigned)((e0+1) * D_EDGE) << 32) | (unsigned)(s4.y * D_OUT);
            p = atomicAdd(&g_cursor[d4.z], 1);
            g_list[p] = ((unsigned long long)(unsigned)((e0+2) * D_EDGE) << 32) | (unsigned)(s4.z * D_OUT);
            p = atomicAdd(&g_cursor[d4.w], 1);
            g_list[p] = ((unsigned long long)(unsigned)((e0+3) * D_EDGE) << 32) | (unsigned)(s4.w * D_OUT);
        } else {
            for (int e = e0; e < N_EDGES; ++e) {
                const int p2 = atomicAdd(&g_cursor[dst[e]], 1);
                g_list[p2] = ((unsigned long long)(unsigned)(e * D_EDGE) << 32)
                           | (unsigned)(src[e] * D_OUT);
            }
        }
        return;
    }

    // ---------------- GEMM partition ----------------
    extern __shared__ char smem[];
    uint32_t sbase;
    asm("{ .reg .u64 t; cvta.to.shared.u64 t, %1; cvt.u32.u64 %0, t; }"
        : "=r"(sbase) : "l"(smem));

    __nv_bfloat16* As_hi = (__nv_bfloat16*)(smem + OFF_AS_HI);
    __nv_bfloat16* As_lo = (__nv_bfloat16*)(smem + OFF_AS_LO);

    const int tid  = threadIdx.x;
    const int wid  = tid >> 5;
    const int lane = tid & 31;
    const int warp_m = wid & 3;      // 4 warps in M (32 rows each)
    const int warp_n = wid >> 2;     // 4 warps in N (64 cols each)
    const int rowBase = blockIdx.x * TILE_M;

    const int arow  = tid >> 2;
    const int acol  = (tid & 3) * 8;
    const int agrow = rowBase + arow;
    const int brow = tid >> 4;           // 0..31
    const int bcol = (tid & 15) * 16;    // 0..240
    const int bOff2 = (brow * LDB + bcol) * 2;   // byte offset in B buffer

    wmma::fragment<wmma::accumulator, 16, 16, 16, float> acc[2][4];
    #pragma unroll
    for (int m = 0; m < 2; m++)
        #pragma unroll
        for (int n = 0; n < 4; n++)
            wmma::fill_fragment(acc[m][n], 0.0f);

    float4 pa[2];
    #pragma unroll
    for (int j = 0; j < 2; j++)
        pa[j] = (agrow < N_NODES)
              ? *(const float4*)(X + (size_t)agrow * D_IN + acol + j * 4)
              : make_float4(0.f, 0.f, 0.f, 0.f);

    // Issue B chunk 0 into buffer 0.
    {
        const uint32_t bb = sbase + OFF_BS;
        const int g = brow * 256 + bcol;
        cp_async16(bb + bOff2,                 g_Whi + g);
        cp_async16(bb + bOff2 + 16,            g_Whi + g + 8);
        cp_async16(bb + BS_BYTES + bOff2,      g_Wlo + g);
        cp_async16(bb + BS_BYTES + bOff2 + 16, g_Wlo + g + 8);
        CP_COMMIT();
    }

    for (int c = 0; c < NCHUNK; ++c) {
        // ---- A: prefetched fp32 -> bf16 hi/lo -> smem (single buffer) ----
        #pragma unroll
        for (int j = 0; j < 2; j++) {
            __nv_bfloat16 h0,h1,h2,h3,l0,l1,l2,l3;
            split_bf16(pa[j].x, h0, l0); split_bf16(pa[j].y, h1, l1);
            split_bf16(pa[j].z, h2, l2); split_bf16(pa[j].w, h3, l3);
            const int o = arow * LDA + acol + j * 4;
            *(uint2*)(As_hi + o) = make_uint2(pack_bf16(h0,h1), pack_bf16(h2,h3));
            *(uint2*)(As_lo + o) = make_uint2(pack_bf16(l0,l1), pack_bf16(l2,l3));
        }

        // ---- Issue B chunk c+1 into the other buffer ----
        if (c + 1 < NCHUNK) {
            const uint32_t bb = sbase + OFF_BS + ((c + 1) & 1) * BBUF_STRIDE;
            const int g = ((c + 1) * KC + brow) * 256 + bcol;
            cp_async16(bb + bOff2,                 g_Whi + g);
            cp_async16(bb + bOff2 + 16,            g_Whi + g + 8);
            cp_async16(bb + BS_BYTES + bOff2,      g_Wlo + g);
            cp_async16(bb + BS_BYTES + bOff2 + 16, g_Wlo + g + 8);
            CP_COMMIT();
            CP_WAIT(1);     // chunk c's group complete
        } else {
            CP_WAIT(0);
        }
        __syncthreads();

        // ---- Prefetch next A chunk (overlaps with MMAs below) ----
        if (c + 1 < NCHUNK) {
            const int k0 = (c + 1) * KC;
            #pragma unroll
            for (int j = 0; j < 2; j++)
                pa[j] = (agrow < N_NODES)
                      ? *(const float4*)(X + (size_t)agrow * D_IN + k0 + acol + j * 4)
                      : make_float4(0.f, 0.f, 0.f, 0.f);
        }

        const __nv_bfloat16* Bs_hi =
            (const __nv_bfloat16*)(smem + OFF_BS + (c & 1) * BBUF_STRIDE);
        const __nv_bfloat16* Bs_lo =
            (const __nv_bfloat16*)(smem + OFF_BS + (c & 1) * BBUF_STRIDE + BS_BYTES);

        // ---- MMAs on this chunk ----
        #pragma unroll
        for (int ks = 0; ks < KC / 16; ks++) {
            wmma::fragment<wmma::matrix_a, 16, 16, 16, __nv_bfloat16, wmma::row_major> a_hi[2], a_lo[2];
            #pragma unroll
            for (int m = 0; m < 2; m++) {
                wmma::load_matrix_sync(a_hi[m], As_hi + (warp_m * 32 + m * 16) * LDA + ks * 16, LDA);
                wmma::load_matrix_sync(a_lo[m], As_lo + (warp_m * 32 + m * 16) * LDA + ks * 16, LDA);
            }
            #pragma unroll
            for (int n = 0; n < 4; n++) {
                wmma::fragment<wmma::matrix_b, 16, 16, 16, __nv_bfloat16, wmma::row_major> b_hi, b_lo;
                wmma::load_matrix_sync(b_hi, Bs_hi + (ks * 16) * LDB + warp_n * 64 + n * 16, LDB);
                wmma::load_matrix_sync(b_lo, Bs_lo + (ks * 16) * LDB + warp_n * 64 + n * 16, LDB);
                #pragma unroll
                for (int m = 0; m < 2; m++) {
                    wmma::mma_sync(acc[m][n], a_hi[m], b_hi, acc[m][n]);
                    wmma::mma_sync(acc[m][n], a_hi[m], b_lo, acc[m][n]);
                    wmma::mma_sync(acc[m][n], a_lo[m], b_hi, acc[m][n]);
                }
            }
        }
        __syncthreads();
    }

    // ---- Epilogue: cols 0-127 -> g_Hb (bf16, staged), 128-255 -> out (fp32) ----
    const bool fullTile = (rowBase + TILE_M <= N_NODES);
    float* stage = (float*)smem + wid * 256;   // per-warp 1KB
    #pragma unroll
    for (int m = 0; m < 2; m++)
        #pragma unroll
        for (int n = 0; n < 4; n++) {
            const int row = rowBase + warp_m * 32 + m * 16;
            const int col = warp_n * 64 + n * 16;
            if (col < 128) {
                wmma::store_matrix_sync(stage, acc[m][n], 16, wmma::mem_row_major);
                __syncwarp();
                const int r  = lane >> 1;
                const int cc = (lane & 1) * 8;
                const int grow = row + r;
                if (grow < N_NODES) {
                    float4 a = *(float4*)(stage + r * 16 + cc + 0);
                    float4 b2 = *(float4*)(stage + r * 16 + cc + 4);
                    uint4 v = make_uint4(
                        pack_bf16(__float2bfloat16(a.x),  __float2bfloat16(a.y)),
                        pack_bf16(__float2bfloat16(a.z),  __float2bfloat16(a.w)),
                        pack_bf16(__float2bfloat16(b2.x), __float2bfloat16(b2.y)),
                        pack_bf16(__float2bfloat16(b2.z), __float2bfloat16(b2.w)));
                    *(uint4*)(g_Hb + (size_t)grow * D_OUT + col + cc) = v;
                }
                __syncwarp();
            } else if (fullTile) {
                wmma::store_matrix_sync(out + (size_t)row * D_OUT + (col - 128),
                                        acc[m][n], D_OUT, wmma::mem_row_major);
            } else {
                wmma::store_matrix_sync(stage, acc[m][n], 16, wmma::mem_row_major);
                __syncwarp();
                const int r  = lane >> 1;
                const int cc = (lane & 1) * 8;
                const int grow = row + r;
                if (grow < N_NODES) {
                    float* p = out + (size_t)grow * D_OUT + (col - 128) + cc;
                    *(float4*)(p + 0) = *(float4*)(stage + r * 16 + cc + 0);
                    *(float4*)(p + 4) = *(float4*)(stage + r * 16 + cc + 4);
                }
                __syncwarp();
            }
        }
}

// ---------------------------------------------------------------------------
// Aggregate: one warp per dst node (grid-stride). Atomic-free, 8-edge unroll.
// H accumulation uses packed f32x2 adds (halves the FADD count).
// ---------------------------------------------------------------------------
__global__ __launch_bounds__(256, 4)
void aggregate_kernel(const float* __restrict__ Xe,
                      const float* __restrict__ We,    // [16][128]
                      const float* __restrict__ bias,
                      float* __restrict__ out) {
    __shared__ float4 sW[D_EDGE][32];   // [k][lane], 8KB

    const int tid  = threadIdx.x;
    const int lane = tid & 31;
    const int col  = lane * 4;

    for (int i = tid; i < D_EDGE * 32; i += 256) {
        const int k = i >> 5, l = i & 31;
        sW[k][l] = *(const float4*)(We + k * D_OUT + l * 4);
    }
    __syncthreads();

    const float4 b = *(const float4*)(bias + col);

    const int warpId = (blockIdx.x * blockDim.x + tid) >> 5;
    const int nWarps = (gridDim.x * blockDim.x) >> 5;

    for (int d = warpId; d < N_NODES; d += nWarps) {
        const int start = g_off[d];
        const int c     = g_deg[d];

        unsigned long long h01 = 0ull, h23 = 0ull;   // packed f32x2 accumulators
        float xacc0 = 0.f, xacc1 = 0.f, xacc2 = 0.f, xacc3 = 0.f;
        const int xl = lane & 15;

        int i = 0;
        for (; i + 8 <= c; i += 8) {
            unsigned long long pe[8];
            #pragma unroll
            for (int j = 0; j < 8; j++) pe[j] = g_list[start + i + j];

            uint2 hu[8];
            #pragma unroll
            for (int j = 0; j < 8; j++)
                hu[j] = *(const uint2*)(g_Hb + (unsigned)pe[j] + col);

            const unsigned eA = (lane < 16) ? (unsigned)(pe[0] >> 32) : (unsigned)(pe[1] >> 32);
            const unsigned eB = (lane < 16) ? (unsigned)(pe[2] >> 32) : (unsigned)(pe[3] >> 32);
            const unsigned eC = (lane < 16) ? (unsigned)(pe[4] >> 32) : (unsigned)(pe[5] >> 32);
            const unsigned eD = (lane < 16) ? (unsigned)(pe[6] >> 32) : (unsigned)(pe[7] >> 32);
            xacc0 += Xe[eA + xl];
            xacc1 += Xe[eB + xl];
            xacc2 += Xe[eC + xl];
            xacc3 += Xe[eD + xl];

            #pragma unroll
            for (int j = 0; j < 8; j++) {
                addx2(h01, bf2_to_f32x2(hu[j].x));
                addx2(h23, bf2_to_f32x2(hu[j].y));
            }
        }
        for (; i + 2 <= c; i += 2) {
            const unsigned long long pe0 = g_list[start + i + 0];
            const unsigned long long pe1 = g_list[start + i + 1];
            const uint2 h0 = *(const uint2*)(g_Hb + (unsigned)pe0 + col);
            const uint2 h1 = *(const uint2*)(g_Hb + (unsigned)pe1 + col);
            const unsigned e = (lane < 16) ? (unsigned)(pe0 >> 32) : (unsigned)(pe1 >> 32);
            xacc0 += Xe[e + xl];
            addx2(h01, bf2_to_f32x2(h0.x));
            addx2(h23, bf2_to_f32x2(h0.y));
            addx2(h01, bf2_to_f32x2(h1.x));
            addx2(h23, bf2_to_f32x2(h1.y));
        }
        if (i < c) {
            const unsigned long long pe = g_list[start + i];
            const uint2 hv = *(const uint2*)(g_Hb + (unsigned)pe + col);
            addx2(h01, bf2_to_f32x2(hv.x));
            addx2(h23, bf2_to_f32x2(hv.y));
            if (lane < 16) xacc0 += Xe[(unsigned)(pe >> 32) + xl];
        }

        float4 o = *(const float4*)(out + (size_t)d * D_OUT + col);
        o.x += b.x; o.y += b.y; o.z += b.z; o.w += b.w;

        if (c > 0) {
            const float2 f01 = *reinterpret_cast<float2*>(&h01);
            const float2 f23 = *reinterpret_cast<float2*>(&h23);
            const float xs = (xacc0 + xacc1) + (xacc2 + xacc3);
            float4 p = make_float4(0.f, 0.f, 0.f, 0.f);
            #pragma unroll
            for (int k = 0; k < D_EDGE; k++) {
                const float xk = __shfl_sync(0xFFFFFFFFu, xs, k) +
                                 __shfl_sync(0xFFFFFFFFu, xs, k + 16);
                const float4 wk = sW[k][lane];
                p.x = fmaf(xk, wk.x, p.x);
                p.y = fmaf(xk, wk.y, p.y);
                p.z = fmaf(xk, wk.z, p.z);
                p.w = fmaf(xk, wk.w, p.w);
            }
            const float inv = 1.0f / (float)c;
            o.x = fmaf(f01.x + p.x, inv, o.x);
            o.y = fmaf(f01.y + p.y, inv, o.y);
            o.z = fmaf(f23.x + p.z, inv, o.z);
            o.w = fmaf(f23.y + p.w, inv, o.w);
        }
        *(float4*)(out + (size_t)d * D_OUT + col) = o;
    }
}

// ---------------------------------------------------------------------------
// Launch
// ---------------------------------------------------------------------------
extern "C" void kernel_launch(void* const* d_in, const int* in_sizes, int n_in,
                              void* d_out, int out_size) {
    const float* X    = (const float*)d_in[0];
    const float* Xe   = (const float*)d_in[1];
    const float* Wn   = (const float*)d_in[2];
    const float* Ws   = (const float*)d_in[3];
    const float* bias = (const float*)d_in[4];
    const float* We   = (const float*)d_in[5];
    const int*   src  = (const int*)d_in[6];
    const int*   dst  = (const int*)d_in[7];
    float*       out  = (float*)d_out;

    cudaFuncSetAttribute(gemm_scatter_kernel,
                         cudaFuncAttributeMaxDynamicSharedMemorySize, GEMM_SMEM);

    // 1) zero degree array + scan-base counter (memset node, no kernel)
    void* degAddr = nullptr;
    cudaGetSymbolAddress(&degAddr, g_deg);
    cudaMemsetAsync(degAddr, 0, (N_NODES + 1) * sizeof(int));

    // 2) fused W pre-split + dst histogram
    prep_kernel<<<64 + HIST_BLOCKS, 256>>>(Wn, Ws, dst);

    // 3) one-shot scan (shfl scan + atomic base grab)
    scan_kernel<<<SCAN_NB, SCAN_BLK>>>();

    // 4) fused: node GEMM (g_Hb = bf16(X@Wn) ; out = X@Ws) + CSR scatter
    gemm_scatter_kernel<<<GEMM_BLOCKS + SCAT_BLOCKS, 512, GEMM_SMEM>>>(
        X, out, src, dst);

    // 5) gather aggregation (fuses mean, edge projection, bias, final combine)
    aggregate_kernel<<<2048, 256>>>(Xe, We, bias, out);
}

// round 15
// speedup vs baseline: 1.0839x; 1.0552x over previous
#include <cuda_runtime.h>
#include <cuda_bf16.h>
#include <mma.h>
#include <cstdint>

using namespace nvcuda;

#define N_NODES 100000
#define N_EDGES 1600000
#define D_IN    256
#define D_EDGE  16
#define D_OUT   128

#define SCAN_BLK  1024
#define SCAN_NB   ((N_NODES + SCAN_BLK - 1) / SCAN_BLK)   // 98

// Scratch (allocation-free rule: __device__ globals)
__device__ __nv_bfloat16      g_Hb[(size_t)N_NODES * D_OUT]; // X @ W_neigh (bf16)
__device__ __nv_bfloat16      g_Whi[D_IN * 256];             // [k][c]: c<128 Wn, else Ws (hi)
__device__ __nv_bfloat16      g_Wlo[D_IN * 256];             // (lo)
__device__ int                g_deg[N_NODES + 1];            // in-degree; [N_NODES] = scan base
__device__ int                g_off[N_NODES];                // CSR offsets
__device__ int                g_cursor[N_NODES];             // scatter cursors
__device__ unsigned long long g_list[N_EDGES];               // packed (e*16)<<32 | (s*128)

__device__ __forceinline__ uint32_t pack_bf16(__nv_bfloat16 a, __nv_bfloat16 b) {
    __nv_bfloat162 t(a, b);
    return *reinterpret_cast<uint32_t*>(&t);
}
__device__ __forceinline__ void split_bf16(float x, __nv_bfloat16& hi, __nv_bfloat16& lo) {
    hi = __float2bfloat16(x);
    lo = __float2bfloat16(x - __bfloat162float(hi));
}
__device__ __forceinline__ void cp_async16(uint32_t smem_addr, const void* gptr) {
    asm volatile("cp.async.cg.shared.global [%0], [%1], 16;"
                 :: "r"(smem_addr), "l"(gptr));
}
#define CP_COMMIT() asm volatile("cp.async.commit_group;")
#define CP_WAIT(n)  asm volatile("cp.async.wait_group %0;" :: "n"(n))

// ---------------------------------------------------------------------------
// Fused prep: blocks [0,64) = W pre-split; blocks [64, ..) = dst histogram.
// ---------------------------------------------------------------------------
#define HIST_BLOCKS ((N_EDGES / 4 + 255) / 256)   // 1563

__global__ __launch_bounds__(256)
void prep_kernel(const float* __restrict__ Wn, const float* __restrict__ Ws,
                 const int* __restrict__ dst) {
    if (blockIdx.x < 64) {
        const int i = blockIdx.x * 256 + threadIdx.x;
        const int k = i >> 6;            // 0..255
        const int c = (i & 63) * 4;      // 0..252
        const float4 v = (c < 128)
                       ? *(const float4*)(Wn + (size_t)k * D_OUT + c)
                       : *(const float4*)(Ws + (size_t)k * D_OUT + (c - 128));
        __nv_bfloat16 h0,h1,h2,h3,l0,l1,l2,l3;
        split_bf16(v.x, h0, l0); split_bf16(v.y, h1, l1);
        split_bf16(v.z, h2, l2); split_bf16(v.w, h3, l3);
        *(uint2*)(g_Whi + k * 256 + c) = make_uint2(pack_bf16(h0,h1), pack_bf16(h2,h3));
        *(uint2*)(g_Wlo + k * 256 + c) = make_uint2(pack_bf16(l0,l1), pack_bf16(l2,l3));
    } else {
        const int i = (blockIdx.x - 64) * 256 + threadIdx.x;
        if (i * 4 + 3 < N_EDGES) {
            const int4 d4 = *(const int4*)(dst + i * 4);
            atomicAdd(&g_deg[d4.x], 1);
            atomicAdd(&g_deg[d4.y], 1);
            atomicAdd(&g_deg[d4.z], 1);
            atomicAdd(&g_deg[d4.w], 1);
        } else {
            for (int e = i * 4; e < N_EDGES; ++e)
                atomicAdd(&g_deg[dst[e]], 1);
        }
    }
}

// ---------------------------------------------------------------------------
// CSR: one-shot scan. Warp-shfl scan + block combine + atomic base grab.
// ---------------------------------------------------------------------------
__global__ __launch_bounds__(SCAN_BLK)
void scan_kernel() {
    __shared__ int wsum[32];
    __shared__ int base;
    const int t = threadIdx.x;
    const int w = t >> 5;
    const int lane = t & 31;
    const int i = blockIdx.x * SCAN_BLK + t;
    const int d = (i < N_NODES) ? g_deg[i] : 0;

    int v = d;
    #pragma unroll
    for (int off = 1; off < 32; off <<= 1) {
        const int u = __shfl_up_sync(0xFFFFFFFFu, v, off);
        if (lane >= off) v += u;
    }
    if (lane == 31) wsum[w] = v;
    __syncthreads();
    if (w == 0) {
        int s = wsum[lane];
        #pragma unroll
        for (int off = 1; off < 32; off <<= 1) {
            const int u = __shfl_up_sync(0xFFFFFFFFu, s, off);
            if (lane >= off) s += u;
        }
        wsum[lane] = s;
        if (lane == 31) base = atomicAdd(&g_deg[N_NODES], s);
    }
    __syncthreads();
    if (i < N_NODES) {
        const int pre = (w > 0) ? wsum[w - 1] : 0;
        const int o = base + pre + v - d;
        g_off[i] = o;
        g_cursor[i] = o;
    }
}

// ---------------------------------------------------------------------------
// Fused launch: blocks [0, GEMM_BLOCKS) = wmma node GEMM (TILE_M=128, 512thr,
// single-buffer A, cp.async double-buffered B), rest = CSR scatter (int4).
// ---------------------------------------------------------------------------
#define TILE_M 128
#define KC     32
#define NCHUNK (D_IN / KC)   // 8
#define LDA    40            // As row stride (bf16), 80B
#define LDB    264           // Bs row stride (bf16), 528B
#define OFF_AS_HI 0
#define OFF_AS_LO 10240
#define OFF_BS    20480
#define BS_BYTES  16896      // 32 * 264 * 2
#define BBUF_STRIDE (2 * BS_BYTES)   // hi+lo per buffer = 33792
#define GEMM_SMEM (OFF_BS + 2 * BBUF_STRIDE)   // 88064

#define GEMM_BLOCKS ((N_NODES + TILE_M - 1) / TILE_M)        // 782
#define SCAT_BLOCKS ((N_EDGES / 4 + 511) / 512)              // 782

__global__ __launch_bounds__(512)
void gemm_scatter_kernel(const float* __restrict__ X,
                         float* __restrict__ out,
                         const int* __restrict__ src,
                         const int* __restrict__ dst) {
    // ---------------- scatter partition (4 edges per thread, int4) ----------
    if (blockIdx.x >= GEMM_BLOCKS) {
        const int q = (blockIdx.x - GEMM_BLOCKS) * 512 + threadIdx.x;
        const int e0 = q * 4;
        if (e0 + 3 < N_EDGES) {
            const int4 s4 = ((const int4*)src)[q];
            const int4 d4 = ((const int4*)dst)[q];
            int p;
            p = atomicAdd(&g_cursor[d4.x], 1);
            g_list[p] = ((unsigned long long)(unsigned)((e0+0) * D_EDGE) << 32) | (unsigned)(s4.x * D_OUT);
            p = atomicAdd(&g_cursor[d4.y], 1);
            g_list[p] = ((unsigned long long)(unsigned)((e0+1) * D_EDGE) << 32) | (unsigned)(s4.y * D_OUT);
            p = atomicAdd(&g_cursor[d4.z], 1);
            g_list[p] = ((unsigned long long)(unsigned)((e0+2) * D_EDGE) << 32) | (unsigned)(s4.z * D_OUT);
            p = atomicAdd(&g_cursor[d4.w], 1);
            g_list[p] = ((unsigned long long)(unsigned)((e0+3) * D_EDGE) << 32) | (unsigned)(s4.w * D_OUT);
        } else {
            for (int e = e0; e < N_EDGES; ++e) {
                const int p2 = atomicAdd(&g_cursor[dst[e]], 1);
                g_list[p2] = ((unsigned long long)(unsigned)(e * D_EDGE) << 32)
                           | (unsigned)(src[e] * D_OUT);
            }
        }
        return;
    }

    // ---------------- GEMM partition ----------------
    extern __shared__ char smem[];
    uint32_t sbase;
    asm("{ .reg .u64 t; cvta.to.shared.u64 t, %1; cvt.u32.u64 %0, t; }"
        : "=r"(sbase) : "l"(smem));

    __nv_bfloat16* As_hi = (__nv_bfloat16*)(smem + OFF_AS_HI);
    __nv_bfloat16* As_lo = (__nv_bfloat16*)(smem + OFF_AS_LO);

    const int tid  = threadIdx.x;
    const int wid  = tid >> 5;
    const int lane = tid & 31;
    const int warp_m = wid & 3;      // 4 warps in M (32 rows each)
    const int warp_n = wid >> 2;     // 4 warps in N (64 cols each)
    const int rowBase = blockIdx.x * TILE_M;

    const int arow  = tid >> 2;
    const int acol  = (tid & 3) * 8;
    const int agrow = rowBase + arow;
    const int brow = tid >> 4;           // 0..31
    const int bcol = (tid & 15) * 16;    // 0..240
    const int bOff2 = (brow * LDB + bcol) * 2;   // byte offset in B buffer

    wmma::fragment<wmma::accumulator, 16, 16, 16, float> acc[2][4];
    #pragma unroll
    for (int m = 0; m < 2; m++)
        #pragma unroll
        for (int n = 0; n < 4; n++)
            wmma::fill_fragment(acc[m][n], 0.0f);

    float4 pa[2];
    #pragma unroll
    for (int j = 0; j < 2; j++)
        pa[j] = (agrow < N_NODES)
              ? *(const float4*)(X + (size_t)agrow * D_IN + acol + j * 4)
              : make_float4(0.f, 0.f, 0.f, 0.f);

    // Issue B chunk 0 into buffer 0.
    {
        const uint32_t bb = sbase + OFF_BS;
        const int g = brow * 256 + bcol;
        cp_async16(bb + bOff2,                 g_Whi + g);
        cp_async16(bb + bOff2 + 16,            g_Whi + g + 8);
        cp_async16(bb + BS_BYTES + bOff2,      g_Wlo + g);
        cp_async16(bb + BS_BYTES + bOff2 + 16, g_Wlo + g + 8);
        CP_COMMIT();
    }

    for (int c = 0; c < NCHUNK; ++c) {
        // ---- A: prefetched fp32 -> bf16 hi/lo -> smem (single buffer) ----
        #pragma unroll
        for (int j = 0; j < 2; j++) {
            __nv_bfloat16 h0,h1,h2,h3,l0,l1,l2,l3;
            split_bf16(pa[j].x, h0, l0); split_bf16(pa[j].y, h1, l1);
            split_bf16(pa[j].z, h2, l2); split_bf16(pa[j].w, h3, l3);
            const int o = arow * LDA + acol + j * 4;
            *(uint2*)(As_hi + o) = make_uint2(pack_bf16(h0,h1), pack_bf16(h2,h3));
            *(uint2*)(As_lo + o) = make_uint2(pack_bf16(l0,l1), pack_bf16(l2,l3));
        }

        // ---- Issue B chunk c+1 into the other buffer ----
        if (c + 1 < NCHUNK) {
            const uint32_t bb = sbase + OFF_BS + ((c + 1) & 1) * BBUF_STRIDE;
            const int g = ((c + 1) * KC + brow) * 256 + bcol;
            cp_async16(bb + bOff2,                 g_Whi + g);
            cp_async16(bb + bOff2 + 16,            g_Whi + g + 8);
            cp_async16(bb + BS_BYTES + bOff2,      g_Wlo + g);
            cp_async16(bb + BS_BYTES + bOff2 + 16, g_Wlo + g + 8);
            CP_COMMIT();
            CP_WAIT(1);     // chunk c's group complete
        } else {
            CP_WAIT(0);
        }
        __syncthreads();

        // ---- Prefetch next A chunk (overlaps with MMAs below) ----
        if (c + 1 < NCHUNK) {
            const int k0 = (c + 1) * KC;
            #pragma unroll
            for (int j = 0; j < 2; j++)
                pa[j] = (agrow < N_NODES)
                      ? *(const float4*)(X + (size_t)agrow * D_IN + k0 + acol + j * 4)
                      : make_float4(0.f, 0.f, 0.f, 0.f);
        }

        const __nv_bfloat16* Bs_hi =
            (const __nv_bfloat16*)(smem + OFF_BS + (c & 1) * BBUF_STRIDE);
        const __nv_bfloat16* Bs_lo =
            (const __nv_bfloat16*)(smem + OFF_BS + (c & 1) * BBUF_STRIDE + BS_BYTES);

        // ---- MMAs on this chunk ----
        #pragma unroll
        for (int ks = 0; ks < KC / 16; ks++) {
            wmma::fragment<wmma::matrix_a, 16, 16, 16, __nv_bfloat16, wmma::row_major> a_hi[2], a_lo[2];
            #pragma unroll
            for (int m = 0; m < 2; m++) {
                wmma::load_matrix_sync(a_hi[m], As_hi + (warp_m * 32 + m * 16) * LDA + ks * 16, LDA);
                wmma::load_matrix_sync(a_lo[m], As_lo + (warp_m * 32 + m * 16) * LDA + ks * 16, LDA);
            }
            #pragma unroll
            for (int n = 0; n < 4; n++) {
                wmma::fragment<wmma::matrix_b, 16, 16, 16, __nv_bfloat16, wmma::row_major> b_hi, b_lo;
                wmma::load_matrix_sync(b_hi, Bs_hi + (ks * 16) * LDB + warp_n * 64 + n * 16, LDB);
                wmma::load_matrix_sync(b_lo, Bs_lo + (ks * 16) * LDB + warp_n * 64 + n * 16, LDB);
                #pragma unroll
                for (int m = 0; m < 2; m++) {
                    wmma::mma_sync(acc[m][n], a_hi[m], b_hi, acc[m][n]);
                    wmma::mma_sync(acc[m][n], a_hi[m], b_lo, acc[m][n]);
                    wmma::mma_sync(acc[m][n], a_lo[m], b_hi, acc[m][n]);
                }
            }
        }
        __syncthreads();
    }

    // ---- Epilogue: cols 0-127 -> g_Hb (bf16, staged), 128-255 -> out (fp32) ----
    const bool fullTile = (rowBase + TILE_M <= N_NODES);
    float* stage = (float*)smem + wid * 256;   // per-warp 1KB
    #pragma unroll
    for (int m = 0; m < 2; m++)
        #pragma unroll
        for (int n = 0; n < 4; n++) {
            const int row = rowBase + warp_m * 32 + m * 16;
            const int col = warp_n * 64 + n * 16;
            if (col < 128) {
                wmma::store_matrix_sync(stage, acc[m][n], 16, wmma::mem_row_major);
                __syncwarp();
                const int r  = lane >> 1;
                const int cc = (lane & 1) * 8;
                const int grow = row + r;
                if (grow < N_NODES) {
                    float4 a = *(float4*)(stage + r * 16 + cc + 0);
                    float4 b2 = *(float4*)(stage + r * 16 + cc + 4);
                    uint4 v = make_uint4(
                        pack_bf16(__float2bfloat16(a.x),  __float2bfloat16(a.y)),
                        pack_bf16(__float2bfloat16(a.z),  __float2bfloat16(a.w)),
                        pack_bf16(__float2bfloat16(b2.x), __float2bfloat16(b2.y)),
                        pack_bf16(__float2bfloat16(b2.z), __float2bfloat16(b2.w)));
                    *(uint4*)(g_Hb + (size_t)grow * D_OUT + col + cc) = v;
                }
                __syncwarp();
            } else if (fullTile) {
                wmma::store_matrix_sync(out + (size_t)row * D_OUT + (col - 128),
                                        acc[m][n], D_OUT, wmma::mem_row_major);
            } else {
                wmma::store_matrix_sync(stage, acc[m][n], 16, wmma::mem_row_major);
                __syncwarp();
                const int r  = lane >> 1;
                const int cc = (lane & 1) * 8;
                const int grow = row + r;
                if (grow < N_NODES) {
                    float* p = out + (size_t)grow * D_OUT + (col - 128) + cc;
                    *(float4*)(p + 0) = *(float4*)(stage + r * 16 + cc + 0);
                    *(float4*)(p + 4) = *(float4*)(stage + r * 16 + cc + 4);
                }
                __syncwarp();
            }
        }
}

// ---------------------------------------------------------------------------
// Aggregate: one warp per dst node (grid-stride). Atomic-free.
// 8 pe loads in flight; hu consumed in two batches of 4 (fewer live regs ->
// 5 CTAs/SM target). Float4 independent accumulation (R12 arithmetic).
// ---------------------------------------------------------------------------
__device__ __forceinline__ void acc_bf16x4(float4& h, uint2 u) {
    const float2 a = __bfloat1622float2(*reinterpret_cast<__nv_bfloat162*>(&u.x));
    const float2 b = __bfloat1622float2(*reinterpret_cast<__nv_bfloat162*>(&u.y));
    h.x += a.x; h.y += a.y; h.z += b.x; h.w += b.y;
}

__global__ __launch_bounds__(256, 5)
void aggregate_kernel(const float* __restrict__ Xe,
                      const float* __restrict__ We,    // [16][128]
                      const float* __restrict__ bias,
                      float* __restrict__ out) {
    __shared__ float4 sW[D_EDGE][32];   // [k][lane], 8KB

    const int tid  = threadIdx.x;
    const int lane = tid & 31;
    const int col  = lane * 4;

    for (int i = tid; i < D_EDGE * 32; i += 256) {
        const int k = i >> 5, l = i & 31;
        sW[k][l] = *(const float4*)(We + k * D_OUT + l * 4);
    }
    __syncthreads();

    const float4 b = *(const float4*)(bias + col);

    const int warpId = (blockIdx.x * blockDim.x + tid) >> 5;
    const int nWarps = (gridDim.x * blockDim.x) >> 5;

    for (int d = warpId; d < N_NODES; d += nWarps) {
        const int start = g_off[d];
        const int c     = g_deg[d];

        float4 h = make_float4(0.f, 0.f, 0.f, 0.f);
        float xacc0 = 0.f, xacc1 = 0.f, xacc2 = 0.f, xacc3 = 0.f;
        const int xl = lane & 15;

        int i = 0;
        for (; i + 8 <= c; i += 8) {
            unsigned long long pe[8];
            #pragma unroll
            for (int j = 0; j < 8; j++) pe[j] = g_list[start + i + j];

            // batch 1: hu[0..3] + Xe pair A,B
            {
                uint2 hu[4];
                #pragma unroll
                for (int j = 0; j < 4; j++)
                    hu[j] = *(const uint2*)(g_Hb + (unsigned)pe[j] + col);
                const unsigned eA = (lane < 16) ? (unsigned)(pe[0] >> 32) : (unsigned)(pe[1] >> 32);
                const unsigned eB = (lane < 16) ? (unsigned)(pe[2] >> 32) : (unsigned)(pe[3] >> 32);
                xacc0 += Xe[eA + xl];
                xacc1 += Xe[eB + xl];
                #pragma unroll
                for (int j = 0; j < 4; j++) acc_bf16x4(h, hu[j]);
            }
            // batch 2: hu[4..7] + Xe pair C,D
            {
                uint2 hu[4];
                #pragma unroll
                for (int j = 0; j < 4; j++)
                    hu[j] = *(const uint2*)(g_Hb + (unsigned)pe[4 + j] + col);
                const unsigned eC = (lane < 16) ? (unsigned)(pe[4] >> 32) : (unsigned)(pe[5] >> 32);
                const unsigned eD = (lane < 16) ? (unsigned)(pe[6] >> 32) : (unsigned)(pe[7] >> 32);
                xacc2 += Xe[eC + xl];
                xacc3 += Xe[eD + xl];
                #pragma unroll
                for (int j = 0; j < 4; j++) acc_bf16x4(h, hu[j]);
            }
        }
        for (; i + 2 <= c; i += 2) {
            const unsigned long long pe0 = g_list[start + i + 0];
            const unsigned long long pe1 = g_list[start + i + 1];
            const uint2 h0 = *(const uint2*)(g_Hb + (unsigned)pe0 + col);
            const uint2 h1 = *(const uint2*)(g_Hb + (unsigned)pe1 + col);
            const unsigned e = (lane < 16) ? (unsigned)(pe0 >> 32) : (unsigned)(pe1 >> 32);
            xacc0 += Xe[e + xl];
            acc_bf16x4(h, h0);
            acc_bf16x4(h, h1);
        }
        if (i < c) {
            const unsigned long long pe = g_list[start + i];
            const uint2 hv = *(const uint2*)(g_Hb + (unsigned)pe + col);
            acc_bf16x4(h, hv);
            if (lane < 16) xacc0 += Xe[(unsigned)(pe >> 32) + xl];
        }

        float4 o = *(const float4*)(out + (size_t)d * D_OUT + col);
        o.x += b.x; o.y += b.y; o.z += b.z; o.w += b.w;

        if (c > 0) {
            const float xs = (xacc0 + xacc1) + (xacc2 + xacc3);
            float4 p = make_float4(0.f, 0.f, 0.f, 0.f);
            #pragma unroll
            for (int k = 0; k < D_EDGE; k++) {
                const float xk = __shfl_sync(0xFFFFFFFFu, xs, k) +
                                 __shfl_sync(0xFFFFFFFFu, xs, k + 16);
                const float4 wk = sW[k][lane];
                p.x = fmaf(xk, wk.x, p.x);
                p.y = fmaf(xk, wk.y, p.y);
                p.z = fmaf(xk, wk.z, p.z);
                p.w = fmaf(xk, wk.w, p.w);
            }
            const float inv = 1.0f / (float)c;
            o.x = fmaf(h.x + p.x, inv, o.x);
            o.y = fmaf(h.y + p.y, inv, o.y);
            o.z = fmaf(h.z + p.z, inv, o.z);
            o.w = fmaf(h.w + p.w, inv, o.w);
        }
        *(float4*)(out + (size_t)d * D_OUT + col) = o;
    }
}

// ---------------------------------------------------------------------------
// Launch
// ---------------------------------------------------------------------------
extern "C" void kernel_launch(void* const* d_in, const int* in_sizes, int n_in,
                              void* d_out, int out_size) {
    const float* X    = (const float*)d_in[0];
    const float* Xe   = (const float*)d_in[1];
    const float* Wn   = (const float*)d_in[2];
    const float* Ws   = (const float*)d_in[3];
    const float* bias = (const float*)d_in[4];
    const float* We   = (const float*)d_in[5];
    const int*   src  = (const int*)d_in[6];
    const int*   dst  = (const int*)d_in[7];
    float*       out  = (float*)d_out;

    cudaFuncSetAttribute(gemm_scatter_kernel,
                         cudaFuncAttributeMaxDynamicSharedMemorySize, GEMM_SMEM);

    // 1) zero degree array + scan-base counter (memset node, no kernel)
    void* degAddr = nullptr;
    cudaGetSymbolAddress(&degAddr, g_deg);
    cudaMemsetAsync(degAddr, 0, (N_NODES + 1) * sizeof(int));

    // 2) fused W pre-split + dst histogram
    prep_kernel<<<64 + HIST_BLOCKS, 256>>>(Wn, Ws, dst);

    // 3) one-shot scan (shfl scan + atomic base grab)
    scan_kernel<<<SCAN_NB, SCAN_BLK>>>();

    // 4) fused: node GEMM (g_Hb = bf16(X@Wn) ; out = X@Ws) + CSR scatter
    gemm_scatter_kernel<<<GEMM_BLOCKS + SCAT_BLOCKS, 512, GEMM_SMEM>>>(
        X, out, src, dst);

    // 5) gather aggregation (fuses mean, edge projection, bias, final combine)
    aggregate_kernel<<<2560, 256>>>(Xe, We, bias, out);
}

// round 16
// speedup vs baseline: 1.1087x; 1.0229x over previous
#include <cuda_runtime.h>
#include <cuda_bf16.h>
#include <mma.h>
#include <cstdint>

using namespace nvcuda;

#define N_NODES 100000
#define N_EDGES 1600000
#define D_IN    256
#define D_EDGE  16
#define D_OUT   128

#define SCAN_BLK  1024
#define SCAN_NB   ((N_NODES + SCAN_BLK - 1) / SCAN_BLK)   // 98

// Scratch (allocation-free rule: __device__ globals)
__device__ __nv_bfloat16      g_Hb[(size_t)N_NODES * D_OUT]; // X @ W_neigh (bf16)
__device__ __nv_bfloat16      g_Whi[D_IN * 256];             // [k][c]: c<128 Wn, else Ws (hi)
__device__ __nv_bfloat16      g_Wlo[D_IN * 256];             // (lo)
__device__ int                g_deg[N_NODES + 1];            // in-degree; [N_NODES] = scan base
__device__ int                g_off[N_NODES];                // CSR offsets
__device__ int                g_cursor[N_NODES];             // scatter cursors
__device__ unsigned long long g_list[N_EDGES];               // packed (e*16)<<32 | (s*128)

__device__ __forceinline__ uint32_t pack_bf16(__nv_bfloat16 a, __nv_bfloat16 b) {
    __nv_bfloat162 t(a, b);
    return *reinterpret_cast<uint32_t*>(&t);
}
__device__ __forceinline__ void split_bf16(float x, __nv_bfloat16& hi, __nv_bfloat16& lo) {
    hi = __float2bfloat16(x);
    lo = __float2bfloat16(x - __bfloat162float(hi));
}
__device__ __forceinline__ void cp_async16(uint32_t smem_addr, const void* gptr) {
    asm volatile("cp.async.cg.shared.global [%0], [%1], 16;"
                 :: "r"(smem_addr), "l"(gptr));
}
#define CP_COMMIT() asm volatile("cp.async.commit_group;")
#define CP_WAIT(n)  asm volatile("cp.async.wait_group %0;" :: "n"(n))

// ---------------------------------------------------------------------------
// Fused prep: blocks [0,64) = W pre-split; blocks [64, ..) = dst histogram.
// ---------------------------------------------------------------------------
#define HIST_BLOCKS ((N_EDGES / 4 + 255) / 256)   // 1563

__global__ __launch_bounds__(256)
void prep_kernel(const float* __restrict__ Wn, const float* __restrict__ Ws,
                 const int* __restrict__ dst) {
    if (blockIdx.x < 64) {
        const int i = blockIdx.x * 256 + threadIdx.x;
        const int k = i >> 6;            // 0..255
        const int c = (i & 63) * 4;      // 0..252
        const float4 v = (c < 128)
                       ? *(const float4*)(Wn + (size_t)k * D_OUT + c)
                       : *(const float4*)(Ws + (size_t)k * D_OUT + (c - 128));
        __nv_bfloat16 h0,h1,h2,h3,l0,l1,l2,l3;
        split_bf16(v.x, h0, l0); split_bf16(v.y, h1, l1);
        split_bf16(v.z, h2, l2); split_bf16(v.w, h3, l3);
        *(uint2*)(g_Whi + k * 256 + c) = make_uint2(pack_bf16(h0,h1), pack_bf16(h2,h3));
        *(uint2*)(g_Wlo + k * 256 + c) = make_uint2(pack_bf16(l0,l1), pack_bf16(l2,l3));
    } else {
        const int i = (blockIdx.x - 64) * 256 + threadIdx.x;
        if (i * 4 + 3 < N_EDGES) {
            const int4 d4 = *(const int4*)(dst + i * 4);
            atomicAdd(&g_deg[d4.x], 1);
            atomicAdd(&g_deg[d4.y], 1);
            atomicAdd(&g_deg[d4.z], 1);
            atomicAdd(&g_deg[d4.w], 1);
        } else {
            for (int e = i * 4; e < N_EDGES; ++e)
                atomicAdd(&g_deg[dst[e]], 1);
        }
    }
}

// ---------------------------------------------------------------------------
// CSR: one-shot scan. Warp-shfl scan + block combine + atomic base grab.
// ---------------------------------------------------------------------------
__global__ __launch_bounds__(SCAN_BLK)
void scan_kernel() {
    __shared__ int wsum[32];
    __shared__ int base;
    const int t = threadIdx.x;
    const int w = t >> 5;
    const int lane = t & 31;
    const int i = blockIdx.x * SCAN_BLK + t;
    const int d = (i < N_NODES) ? g_deg[i] : 0;

    int v = d;
    #pragma unroll
    for (int off = 1; off < 32; off <<= 1) {
        const int u = __shfl_up_sync(0xFFFFFFFFu, v, off);
        if (lane >= off) v += u;
    }
    if (lane == 31) wsum[w] = v;
    __syncthreads();
    if (w == 0) {
        int s = wsum[lane];
        #pragma unroll
        for (int off = 1; off < 32; off <<= 1) {
            const int u = __shfl_up_sync(0xFFFFFFFFu, s, off);
            if (lane >= off) s += u;
        }
        wsum[lane] = s;
        if (lane == 31) base = atomicAdd(&g_deg[N_NODES], s);
    }
    __syncthreads();
    if (i < N_NODES) {
        const int pre = (w > 0) ? wsum[w - 1] : 0;
        const int o = base + pre + v - d;
        g_off[i] = o;
        g_cursor[i] = o;
    }
}

// ---------------------------------------------------------------------------
// Fused launch: blocks [0, GEMM_BLOCKS) = wmma node GEMM (TILE_M=128, 512thr,
// single-buffer A, cp.async double-buffered B), rest = CSR scatter (int4).
// ---------------------------------------------------------------------------
#define TILE_M 128
#define KC     32
#define NCHUNK (D_IN / KC)   // 8
#define LDA    40            // As row stride (bf16), 80B
#define LDB    264           // Bs row stride (bf16), 528B
#define OFF_AS_HI 0
#define OFF_AS_LO 10240
#define OFF_BS    20480
#define BS_BYTES  16896      // 32 * 264 * 2
#define BBUF_STRIDE (2 * BS_BYTES)   // hi+lo per buffer = 33792
#define GEMM_SMEM (OFF_BS + 2 * BBUF_STRIDE)   // 88064

#define GEMM_BLOCKS ((N_NODES + TILE_M - 1) / TILE_M)        // 782
#define SCAT_BLOCKS ((N_EDGES / 4 + 511) / 512)              // 782

__global__ __launch_bounds__(512)
void gemm_scatter_kernel(const float* __restrict__ X,
                         float* __restrict__ out,
                         const int* __restrict__ src,
                         const int* __restrict__ dst) {
    // ---------------- scatter partition (4 edges per thread, int4) ----------
    if (blockIdx.x >= GEMM_BLOCKS) {
        const int q = (blockIdx.x - GEMM_BLOCKS) * 512 + threadIdx.x;
        const int e0 = q * 4;
        if (e0 + 3 < N_EDGES) {
            const int4 s4 = ((const int4*)src)[q];
            const int4 d4 = ((const int4*)dst)[q];
            int p;
            p = atomicAdd(&g_cursor[d4.x], 1);
            g_list[p] = ((unsigned long long)(unsigned)((e0+0) * D_EDGE) << 32) | (unsigned)(s4.x * D_OUT);
            p = atomicAdd(&g_cursor[d4.y], 1);
            g_list[p] = ((unsigned long long)(unsigned)((e0+1) * D_EDGE) << 32) | (unsigned)(s4.y * D_OUT);
            p = atomicAdd(&g_cursor[d4.z], 1);
            g_list[p] = ((unsigned long long)(unsigned)((e0+2) * D_EDGE) << 32) | (unsigned)(s4.z * D_OUT);
            p = atomicAdd(&g_cursor[d4.w], 1);
            g_list[p] = ((unsigned long long)(unsigned)((e0+3) * D_EDGE) << 32) | (unsigned)(s4.w * D_OUT);
        } else {
            for (int e = e0; e < N_EDGES; ++e) {
                const int p2 = atomicAdd(&g_cursor[dst[e]], 1);
                g_list[p2] = ((unsigned long long)(unsigned)(e * D_EDGE) << 32)
                           | (unsigned)(src[e] * D_OUT);
            }
        }
        return;
    }

    // ---------------- GEMM partition ----------------
    extern __shared__ char smem[];
    uint32_t sbase;
    asm("{ .reg .u64 t; cvta.to.shared.u64 t, %1; cvt.u32.u64 %0, t; }"
        : "=r"(sbase) : "l"(smem));

    __nv_bfloat16* As_hi = (__nv_bfloat16*)(smem + OFF_AS_HI);
    __nv_bfloat16* As_lo = (__nv_bfloat16*)(smem + OFF_AS_LO);

    const int tid  = threadIdx.x;
    const int wid  = tid >> 5;
    const int lane = tid & 31;
    const int warp_m = wid & 3;      // 4 warps in M (32 rows each)
    const int warp_n = wid >> 2;     // 4 warps in N (64 cols each)
    const int rowBase = blockIdx.x * TILE_M;

    const int arow  = tid >> 2;
    const int acol  = (tid & 3) * 8;
    const int agrow = rowBase + arow;
    const int brow = tid >> 4;           // 0..31
    const int bcol = (tid & 15) * 16;    // 0..240
    const int bOff2 = (brow * LDB + bcol) * 2;   // byte offset in B buffer

    wmma::fragment<wmma::accumulator, 16, 16, 16, float> acc[2][4];
    #pragma unroll
    for (int m = 0; m < 2; m++)
        #pragma unroll
        for (int n = 0; n < 4; n++)
            wmma::fill_fragment(acc[m][n], 0.0f);

    float4 pa[2];
    #pragma unroll
    for (int j = 0; j < 2; j++)
        pa[j] = (agrow < N_NODES)
              ? *(const float4*)(X + (size_t)agrow * D_IN + acol + j * 4)
              : make_float4(0.f, 0.f, 0.f, 0.f);

    // Issue B chunk 0 into buffer 0.
    {
        const uint32_t bb = sbase + OFF_BS;
        const int g = brow * 256 + bcol;
        cp_async16(bb + bOff2,                 g_Whi + g);
        cp_async16(bb + bOff2 + 16,            g_Whi + g + 8);
        cp_async16(bb + BS_BYTES + bOff2,      g_Wlo + g);
        cp_async16(bb + BS_BYTES + bOff2 + 16, g_Wlo + g + 8);
        CP_COMMIT();
    }

    for (int c = 0; c < NCHUNK; ++c) {
        // ---- A: prefetched fp32 -> bf16 hi/lo -> smem (single buffer) ----
        #pragma unroll
        for (int j = 0; j < 2; j++) {
            __nv_bfloat16 h0,h1,h2,h3,l0,l1,l2,l3;
            split_bf16(pa[j].x, h0, l0); split_bf16(pa[j].y, h1, l1);
            split_bf16(pa[j].z, h2, l2); split_bf16(pa[j].w, h3, l3);
            const int o = arow * LDA + acol + j * 4;
            *(uint2*)(As_hi + o) = make_uint2(pack_bf16(h0,h1), pack_bf16(h2,h3));
            *(uint2*)(As_lo + o) = make_uint2(pack_bf16(l0,l1), pack_bf16(l2,l3));
        }

        // ---- Issue B chunk c+1 into the other buffer ----
        if (c + 1 < NCHUNK) {
            const uint32_t bb = sbase + OFF_BS + ((c + 1) & 1) * BBUF_STRIDE;
            const int g = ((c + 1) * KC + brow) * 256 + bcol;
            cp_async16(bb + bOff2,                 g_Whi + g);
            cp_async16(bb + bOff2 + 16,            g_Whi + g + 8);
            cp_async16(bb + BS_BYTES + bOff2,      g_Wlo + g);
            cp_async16(bb + BS_BYTES + bOff2 + 16, g_Wlo + g + 8);
            CP_COMMIT();
            CP_WAIT(1);     // chunk c's group complete
        } else {
            CP_WAIT(0);
        }
        __syncthreads();

        // ---- Prefetch next A chunk (overlaps with MMAs below) ----
        if (c + 1 < NCHUNK) {
            const int k0 = (c + 1) * KC;
            #pragma unroll
            for (int j = 0; j < 2; j++)
                pa[j] = (agrow < N_NODES)
                      ? *(const float4*)(X + (size_t)agrow * D_IN + k0 + acol + j * 4)
                      : make_float4(0.f, 0.f, 0.f, 0.f);
        }

        const __nv_bfloat16* Bs_hi =
            (const __nv_bfloat16*)(smem + OFF_BS + (c & 1) * BBUF_STRIDE);
        const __nv_bfloat16* Bs_lo =
            (const __nv_bfloat16*)(smem + OFF_BS + (c & 1) * BBUF_STRIDE + BS_BYTES);

        // ---- MMAs on this chunk ----
        #pragma unroll
        for (int ks = 0; ks < KC / 16; ks++) {
            wmma::fragment<wmma::matrix_a, 16, 16, 16, __nv_bfloat16, wmma::row_major> a_hi[2], a_lo[2];
            #pragma unroll
            for (int m = 0; m < 2; m++) {
                wmma::load_matrix_sync(a_hi[m], As_hi + (warp_m * 32 + m * 16) * LDA + ks * 16, LDA);
                wmma::load_matrix_sync(a_lo[m], As_lo + (warp_m * 32 + m * 16) * LDA + ks * 16, LDA);
            }
            #pragma unroll
            for (int n = 0; n < 4; n++) {
                wmma::fragment<wmma::matrix_b, 16, 16, 16, __nv_bfloat16, wmma::row_major> b_hi, b_lo;
                wmma::load_matrix_sync(b_hi, Bs_hi + (ks * 16) * LDB + warp_n * 64 + n * 16, LDB);
                wmma::load_matrix_sync(b_lo, Bs_lo + (ks * 16) * LDB + warp_n * 64 + n * 16, LDB);
                #pragma unroll
                for (int m = 0; m < 2; m++) {
                    wmma::mma_sync(acc[m][n], a_hi[m], b_hi, acc[m][n]);
                    wmma::mma_sync(acc[m][n], a_hi[m], b_lo, acc[m][n]);
                    wmma::mma_sync(acc[m][n], a_lo[m], b_hi, acc[m][n]);
                }
            }
        }
        __syncthreads();
    }

    // ---- Epilogue: cols 0-127 -> g_Hb (bf16, staged), 128-255 -> out (fp32) ----
    const bool fullTile = (rowBase + TILE_M <= N_NODES);
    float* stage = (float*)smem + wid * 256;   // per-warp 1KB
    #pragma unroll
    for (int m = 0; m < 2; m++)
        #pragma unroll
        for (int n = 0; n < 4; n++) {
            const int row = rowBase + warp_m * 32 + m * 16;
            const int col = warp_n * 64 + n * 16;
            if (col < 128) {
                wmma::store_matrix_sync(stage, acc[m][n], 16, wmma::mem_row_major);
                __syncwarp();
                const int r  = lane >> 1;
                const int cc = (lane & 1) * 8;
                const int grow = row + r;
                if (grow < N_NODES) {
                    float4 a = *(float4*)(stage + r * 16 + cc + 0);
                    float4 b2 = *(float4*)(stage + r * 16 + cc + 4);
                    uint4 v = make_uint4(
                        pack_bf16(__float2bfloat16(a.x),  __float2bfloat16(a.y)),
                        pack_bf16(__float2bfloat16(a.z),  __float2bfloat16(a.w)),
                        pack_bf16(__float2bfloat16(b2.x), __float2bfloat16(b2.y)),
                        pack_bf16(__float2bfloat16(b2.z), __float2bfloat16(b2.w)));
                    *(uint4*)(g_Hb + (size_t)grow * D_OUT + col + cc) = v;
                }
                __syncwarp();
            } else if (fullTile) {
                wmma::store_matrix_sync(out + (size_t)row * D_OUT + (col - 128),
                                        acc[m][n], D_OUT, wmma::mem_row_major);
            } else {
                wmma::store_matrix_sync(stage, acc[m][n], 16, wmma::mem_row_major);
                __syncwarp();
                const int r  = lane >> 1;
                const int cc = (lane & 1) * 8;
                const int grow = row + r;
                if (grow < N_NODES) {
                    float* p = out + (size_t)grow * D_OUT + (col - 128) + cc;
                    *(float4*)(p + 0) = *(float4*)(stage + r * 16 + cc + 0);
                    *(float4*)(p + 4) = *(float4*)(stage + r * 16 + cc + 4);
                }
                __syncwarp();
            }
        }
}

// ---------------------------------------------------------------------------
// Aggregate: one warp per dst node (grid-stride). Atomic-free.
// 8 pe loads in flight; hu consumed in two batches of 4. 6 CTAs/SM target.
// ---------------------------------------------------------------------------
__device__ __forceinline__ void acc_bf16x4(float4& h, uint2 u) {
    const float2 a = __bfloat1622float2(*reinterpret_cast<__nv_bfloat162*>(&u.x));
    const float2 b = __bfloat1622float2(*reinterpret_cast<__nv_bfloat162*>(&u.y));
    h.x += a.x; h.y += a.y; h.z += b.x; h.w += b.y;
}

__global__ __launch_bounds__(256, 6)
void aggregate_kernel(const float* __restrict__ Xe,
                      const float* __restrict__ We,    // [16][128]
                      const float* __restrict__ bias,
                      float* __restrict__ out) {
    __shared__ float4 sW[D_EDGE][32];   // [k][lane], 8KB

    const int tid  = threadIdx.x;
    const int lane = tid & 31;
    const int col  = lane * 4;

    for (int i = tid; i < D_EDGE * 32; i += 256) {
        const int k = i >> 5, l = i & 31;
        sW[k][l] = *(const float4*)(We + k * D_OUT + l * 4);
    }
    __syncthreads();

    const float4 b = *(const float4*)(bias + col);

    const int warpId = (blockIdx.x * blockDim.x + tid) >> 5;
    const int nWarps = (gridDim.x * blockDim.x) >> 5;

    for (int d = warpId; d < N_NODES; d += nWarps) {
        const int start = g_off[d];
        const int c     = g_deg[d];

        float4 h = make_float4(0.f, 0.f, 0.f, 0.f);
        float xacc0 = 0.f, xacc1 = 0.f, xacc2 = 0.f, xacc3 = 0.f;
        const int xl = lane & 15;

        int i = 0;
        for (; i + 8 <= c; i += 8) {
            unsigned long long pe[8];
            #pragma unroll
            for (int j = 0; j < 8; j++) pe[j] = g_list[start + i + j];

            // batch 1: hu[0..3] + Xe pair A,B
            {
                uint2 hu[4];
                #pragma unroll
                for (int j = 0; j < 4; j++)
                    hu[j] = *(const uint2*)(g_Hb + (unsigned)pe[j] + col);
                const unsigned eA = (lane < 16) ? (unsigned)(pe[0] >> 32) : (unsigned)(pe[1] >> 32);
                const unsigned eB = (lane < 16) ? (unsigned)(pe[2] >> 32) : (unsigned)(pe[3] >> 32);
                xacc0 += Xe[eA + xl];
                xacc1 += Xe[eB + xl];
                #pragma unroll
                for (int j = 0; j < 4; j++) acc_bf16x4(h, hu[j]);
            }
            // batch 2: hu[4..7] + Xe pair C,D
            {
                uint2 hu[4];
                #pragma unroll
                for (int j = 0; j < 4; j++)
                    hu[j] = *(const uint2*)(g_Hb + (unsigned)pe[4 + j] + col);
                const unsigned eC = (lane < 16) ? (unsigned)(pe[4] >> 32) : (unsigned)(pe[5] >> 32);
                const unsigned eD = (lane < 16) ? (unsigned)(pe[6] >> 32) : (unsigned)(pe[7] >> 32);
                xacc2 += Xe[eC + xl];
                xacc3 += Xe[eD + xl];
                #pragma unroll
                for (int j = 0; j < 4; j++) acc_bf16x4(h, hu[j]);
            }
        }
        for (; i + 2 <= c; i += 2) {
            const unsigned long long pe0 = g_list[start + i + 0];
            const unsigned long long pe1 = g_list[start + i + 1];
            const uint2 h0 = *(const uint2*)(g_Hb + (unsigned)pe0 + col);
            const uint2 h1 = *(const uint2*)(g_Hb + (unsigned)pe1 + col);
            const unsigned e = (lane < 16) ? (unsigned)(pe0 >> 32) : (unsigned)(pe1 >> 32);
            xacc0 += Xe[e + xl];
            acc_bf16x4(h, h0);
            acc_bf16x4(h, h1);
        }
        if (i < c) {
            const unsigned long long pe = g_list[start + i];
            const uint2 hv = *(const uint2*)(g_Hb + (unsigned)pe + col);
            acc_bf16x4(h, hv);
            if (lane < 16) xacc0 += Xe[(unsigned)(pe >> 32) + xl];
        }

        float4 o = *(const float4*)(out + (size_t)d * D_OUT + col);
        o.x += b.x; o.y += b.y; o.z += b.z; o.w += b.w;

        if (c > 0) {
            const float xs = (xacc0 + xacc1) + (xacc2 + xacc3);
            float4 p = make_float4(0.f, 0.f, 0.f, 0.f);
            #pragma unroll
            for (int k = 0; k < D_EDGE; k++) {
                const float xk = __shfl_sync(0xFFFFFFFFu, xs, k) +
                                 __shfl_sync(0xFFFFFFFFu, xs, k + 16);
                const float4 wk = sW[k][lane];
                p.x = fmaf(xk, wk.x, p.x);
                p.y = fmaf(xk, wk.y, p.y);
                p.z = fmaf(xk, wk.z, p.z);
                p.w = fmaf(xk, wk.w, p.w);
            }
            const float inv = 1.0f / (float)c;
            o.x = fmaf(h.x + p.x, inv, o.x);
            o.y = fmaf(h.y + p.y, inv, o.y);
            o.z = fmaf(h.z + p.z, inv, o.z);
            o.w = fmaf(h.w + p.w, inv, o.w);
        }
        *(float4*)(out + (size_t)d * D_OUT + col) = o;
    }
}

// ---------------------------------------------------------------------------
// Launch
// ---------------------------------------------------------------------------
extern "C" void kernel_launch(void* const* d_in, const int* in_sizes, int n_in,
                              void* d_out, int out_size) {
    const float* X    = (const float*)d_in[0];
    const float* Xe   = (const float*)d_in[1];
    const float* Wn   = (const float*)d_in[2];
    const float* Ws   = (const float*)d_in[3];
    const float* bias = (const float*)d_in[4];
    const float* We   = (const float*)d_in[5];
    const int*   src  = (const int*)d_in[6];
    const int*   dst  = (const int*)d_in[7];
    float*       out  = (float*)d_out;

    cudaFuncSetAttribute(gemm_scatter_kernel,
                         cudaFuncAttributeMaxDynamicSharedMemorySize, GEMM_SMEM);

    // 1) zero degree array + scan-base counter (memset node, no kernel)
    void* degAddr = nullptr;
    cudaGetSymbolAddress(&degAddr, g_deg);
    cudaMemsetAsync(degAddr, 0, (N_NODES + 1) * sizeof(int));

    // 2) fused W pre-split + dst histogram
    prep_kernel<<<64 + HIST_BLOCKS, 256>>>(Wn, Ws, dst);

    // 3) one-shot scan (shfl scan + atomic base grab)
    scan_kernel<<<SCAN_NB, SCAN_BLK>>>();

    // 4) fused: node GEMM (g_Hb = bf16(X@Wn) ; out = X@Ws) + CSR scatter
    gemm_scatter_kernel<<<GEMM_BLOCKS + SCAT_BLOCKS, 512, GEMM_SMEM>>>(
        X, out, src, dst);

    // 5) gather aggregation (fuses mean, edge projection, bias, final combine)
    aggregate_kernel<<<2664, 256>>>(Xe, We, bias, out);
}